// round 1
// baseline (speedup 1.0000x reference)
#include <cuda_runtime.h>
#include <math.h>

// Problem constants (fixed shapes from reference setup_inputs)
#define BATCH 4
#define NPTS  8192
#define ALPHA 1000.0f

// Scratch: __device__ globals (no allocation allowed).
// dir 0: queries = xyz2 (gt), refs = xyz1 (pred)  -> dist1/idx1/count1
// dir 1: queries = xyz1 (pred), refs = xyz2 (gt)  -> dist2/idx2/count2
__device__ float g_dist[2][BATCH][NPTS];
__device__ int   g_idx [2][BATCH][NPTS];
__device__ int   g_cnt [2][BATCH][NPTS];

// ---------------------------------------------------------------------------
// Kernel 1: zero histograms + output scalar
// ---------------------------------------------------------------------------
__global__ void dacd_init_kernel(float* __restrict__ out) {
    int t = blockIdx.x * blockDim.x + threadIdx.x;
    int total = 2 * BATCH * NPTS;
    if (t < total) {
        ((int*)g_cnt)[t] = 0;
    }
    if (t == 0) out[0] = 0.0f;
}

// ---------------------------------------------------------------------------
// Kernel 2: brute-force nearest neighbor, both directions.
// grid: (NPTS/128, BATCH, 2), block: 128 threads, 1 query point per thread.
// Uses d' = ||b||^2 - 2 q.b  (|| q ||^2 added at the end), matching the
// reference's expansion formula.
// ---------------------------------------------------------------------------
#define TILE_J 256

__global__ void __launch_bounds__(128)
dacd_nn_kernel(const float* __restrict__ xyz1, const float* __restrict__ xyz2) {
    const int dir = blockIdx.z;
    const int b   = blockIdx.y;
    const int i   = blockIdx.x * blockDim.x + threadIdx.x;

    const float* __restrict__ q = (dir == 0) ? xyz2 : xyz1;
    const float* __restrict__ r = (dir == 0) ? xyz1 : xyz2;

    __shared__ float4 sm[TILE_J];

    const size_t qoff = ((size_t)b * NPTS + i) * 3;
    const float qx = q[qoff + 0];
    const float qy = q[qoff + 1];
    const float qz = q[qoff + 2];
    const float mx = -2.0f * qx;
    const float my = -2.0f * qy;
    const float mz = -2.0f * qz;
    const float qsq = qx * qx + qy * qy + qz * qz;

    float bestd = INFINITY;
    int   bestj = 0;

    for (int tile = 0; tile < NPTS; tile += TILE_J) {
        __syncthreads();
        // cooperative tile load: 128 threads load 256 points (2 each)
        #pragma unroll
        for (int k = threadIdx.x; k < TILE_J; k += 128) {
            const float* p = r + ((size_t)b * NPTS + tile + k) * 3;
            float x = p[0], y = p[1], z = p[2];
            sm[k] = make_float4(x, y, z, x * x + y * y + z * z);
        }
        __syncthreads();

        #pragma unroll 8
        for (int k = 0; k < TILE_J; k++) {
            float4 v = sm[k];
            float d = fmaf(mx, v.x, fmaf(my, v.y, fmaf(mz, v.z, v.w)));
            if (d < bestd) { bestd = d; bestj = tile + k; }
        }
    }

    const float dist = qsq + bestd;
    g_dist[dir][b][i] = dist;
    g_idx [dir][b][i] = bestj;
    atomicAdd(&g_cnt[dir][b][bestj], 1);
}

// ---------------------------------------------------------------------------
// Kernel 3: density-aware weighting + reduction to scalar.
// 2*BATCH*NPTS = 65536 points; block reduce + atomicAdd.
// frac_21 = n_gt / n_x = 1.0 exactly; ceil(frac_21) = 1.
// weight1 = 1 / max(frac/c + 1e-6, 1)   (c = count at chosen index)
// weight2 = 1 / (c + 1e-6)
// out = sum over all points of (1 - exp(-alpha*d) * w) / (2*B*N)
// ---------------------------------------------------------------------------
__global__ void __launch_bounds__(256)
dacd_loss_kernel(float* __restrict__ out) {
    const int t = blockIdx.x * blockDim.x + threadIdx.x;  // 0 .. 2*B*N-1
    const int dir = t / (BATCH * NPTS);
    const int rem = t % (BATCH * NPTS);
    const int b = rem / NPTS;
    const int i = rem % NPTS;

    float dist = g_dist[dir][b][i];
    int   idx  = g_idx [dir][b][i];
    float c    = (float)g_cnt[dir][b][idx];

    float w;
    if (dir == 0) {
        w = 1.0f / fmaxf(1.0f / c + 1e-6f, 1.0f);
    } else {
        w = 1.0f / (c + 1e-6f);
    }

    float e = expf(-dist * ALPHA);
    float contrib = (1.0f - e * w) * (1.0f / (2.0f * BATCH * NPTS));

    // warp reduce
    #pragma unroll
    for (int off = 16; off > 0; off >>= 1)
        contrib += __shfl_down_sync(0xFFFFFFFFu, contrib, off);

    __shared__ float warp_sums[8];
    const int lane = threadIdx.x & 31;
    const int wid  = threadIdx.x >> 5;
    if (lane == 0) warp_sums[wid] = contrib;
    __syncthreads();

    if (wid == 0) {
        float s = (lane < 8) ? warp_sums[lane] : 0.0f;
        #pragma unroll
        for (int off = 4; off > 0; off >>= 1)
            s += __shfl_down_sync(0xFFFFFFFFu, s, off);
        if (lane == 0) atomicAdd(out, s);
    }
}

// ---------------------------------------------------------------------------
// Launch
// ---------------------------------------------------------------------------
extern "C" void kernel_launch(void* const* d_in, const int* in_sizes, int n_in,
                              void* d_out, int out_size) {
    const float* xyz1 = (const float*)d_in[0];  // prediction [4,8192,3]
    const float* xyz2 = (const float*)d_in[1];  // ground truth [4,8192,3]
    float* out = (float*)d_out;

    (void)in_sizes; (void)n_in; (void)out_size;

    // 1) zero counts + output
    {
        int total = 2 * BATCH * NPTS;
        dacd_init_kernel<<<(total + 255) / 256, 256>>>(out);
    }

    // 2) bidirectional NN (both directions in one launch via grid.z)
    {
        dim3 grid(NPTS / 128, BATCH, 2);
        dacd_nn_kernel<<<grid, 128>>>(xyz1, xyz2);
    }

    // 3) weighting + reduction
    {
        int total = 2 * BATCH * NPTS;
        dacd_loss_kernel<<<total / 256, 256>>>(out);
    }
}

// round 2
// speedup vs baseline: 1.7826x; 1.7826x over previous
#include <cuda_runtime.h>
#include <math.h>

// Problem constants (fixed shapes from reference setup_inputs)
#define BATCH 4
#define NPTS  8192
#define ALPHA 1000.0f

#define TILE_J   256
#define CHUNK    32
#define THR_NN   64
#define IQ       2     // queries per thread

// Scratch (__device__ globals; no allocation allowed).
// g_r4[a][b][j] = (x, y, z, x^2+y^2+z^2) for array a (0 = xyz1/pred, 1 = xyz2/gt)
__device__ float4 g_r4 [2][BATCH][NPTS];
// dir 0: queries = xyz2 (gt),   refs = xyz1 (pred)
// dir 1: queries = xyz1 (pred), refs = xyz2 (gt)
__device__ float  g_dist[2][BATCH][NPTS];
__device__ int    g_idx [2][BATCH][NPTS];
__device__ int    g_cnt [2][BATCH][NPTS];

// ---------------------------------------------------------------------------
// Kernel 1: build float4 point arrays, zero histograms + output scalar
// ---------------------------------------------------------------------------
__global__ void dacd_prep_kernel(const float* __restrict__ xyz1,
                                 const float* __restrict__ xyz2,
                                 float* __restrict__ out) {
    int t = blockIdx.x * blockDim.x + threadIdx.x;   // 0 .. 2*B*N-1
    const int total = 2 * BATCH * NPTS;
    if (t < total) {
        ((int*)g_cnt)[t] = 0;
        const int a   = t / (BATCH * NPTS);
        const int rem = t % (BATCH * NPTS);
        const float* src = (a == 0) ? xyz1 : xyz2;
        float x = src[(size_t)rem * 3 + 0];
        float y = src[(size_t)rem * 3 + 1];
        float z = src[(size_t)rem * 3 + 2];
        ((float4*)g_r4)[t] = make_float4(x, y, z, x * x + y * y + z * z);
    }
    if (t == 0) out[0] = 0.0f;
}

// ---------------------------------------------------------------------------
// Kernel 2: brute-force NN, both directions.
// grid: (NPTS/(THR_NN*IQ), BATCH, 2), block: THR_NN threads, IQ queries/thread.
// Hot loop: 3 FFMA + 1 FMNMX per pair (min value only). Per-CHUNK improvement
// check records the winning 32-point chunk; afterwards that chunk is replayed
// exactly (same FFMA expression -> bitwise-equal d) to recover first-argmin.
// ---------------------------------------------------------------------------
__global__ void __launch_bounds__(THR_NN)
dacd_nn_kernel() {
    const int dir = blockIdx.z;
    const int b   = blockIdx.y;
    const int qarr = (dir == 0) ? 1 : 0;   // dir0 queries = xyz2
    const int rarr = (dir == 0) ? 0 : 1;

    const int i0 = blockIdx.x * (THR_NN * IQ) + threadIdx.x;
    const int i1 = i0 + THR_NN;

    const float4 q0 = g_r4[qarr][b][i0];
    const float4 q1 = g_r4[qarr][b][i1];
    const float mx0 = -2.0f * q0.x, my0 = -2.0f * q0.y, mz0 = -2.0f * q0.z;
    const float mx1 = -2.0f * q1.x, my1 = -2.0f * q1.y, mz1 = -2.0f * q1.z;

    __shared__ float4 sm[TILE_J];

    float bestd0 = INFINITY, bestd1 = INFINITY;
    int   cw0 = 0, cw1 = 0;   // winning chunk index (global, units of CHUNK)

    const float4* __restrict__ refs = &g_r4[rarr][b][0];

    for (int tile = 0; tile < NPTS; tile += TILE_J) {
        __syncthreads();
        #pragma unroll
        for (int k = threadIdx.x; k < TILE_J; k += THR_NN)
            sm[k] = refs[tile + k];
        __syncthreads();

        #pragma unroll 1
        for (int c = 0; c < TILE_J; c += CHUNK) {
            const float p0 = bestd0, p1 = bestd1;
            #pragma unroll
            for (int k = 0; k < CHUNK; k++) {
                float4 v = sm[c + k];
                float d0 = fmaf(mx0, v.x, fmaf(my0, v.y, fmaf(mz0, v.z, v.w)));
                float d1 = fmaf(mx1, v.x, fmaf(my1, v.y, fmaf(mz1, v.z, v.w)));
                bestd0 = fminf(bestd0, d0);
                bestd1 = fminf(bestd1, d1);
            }
            const int cid = (tile + c) >> 5;
            cw0 = (bestd0 < p0) ? cid : cw0;
            cw1 = (bestd1 < p1) ? cid : cw1;
        }
    }

    // Replay winning chunk to find the FIRST index attaining the min (exact).
    {
        const int base = cw0 * CHUNK;
        int bj = 0x7FFFFFFF;
        #pragma unroll 8
        for (int k = 0; k < CHUNK; k++) {
            float4 v = refs[base + k];
            float d = fmaf(mx0, v.x, fmaf(my0, v.y, fmaf(mz0, v.z, v.w)));
            if (d == bestd0) bj = min(bj, base + k);
        }
        g_dist[dir][b][i0] = q0.w + bestd0;
        g_idx [dir][b][i0] = bj;
        atomicAdd(&g_cnt[dir][b][bj], 1);
    }
    {
        const int base = cw1 * CHUNK;
        int bj = 0x7FFFFFFF;
        #pragma unroll 8
        for (int k = 0; k < CHUNK; k++) {
            float4 v = refs[base + k];
            float d = fmaf(mx1, v.x, fmaf(my1, v.y, fmaf(mz1, v.z, v.w)));
            if (d == bestd1) bj = min(bj, base + k);
        }
        g_dist[dir][b][i1] = q1.w + bestd1;
        g_idx [dir][b][i1] = bj;
        atomicAdd(&g_cnt[dir][b][bj], 1);
    }
}

// ---------------------------------------------------------------------------
// Kernel 3: density-aware weighting + reduction to scalar.
// frac_21 = 1.0 exactly; ceil(frac_21) = 1.
// weight1 = 1 / max(1/c + 1e-6, 1),  weight2 = 1 / (c + 1e-6)
// out = sum (1 - exp(-alpha*d) * w) / (2*B*N)
// ---------------------------------------------------------------------------
__global__ void __launch_bounds__(256)
dacd_loss_kernel(float* __restrict__ out) {
    const int t = blockIdx.x * blockDim.x + threadIdx.x;  // 0 .. 2*B*N-1
    const int dir = t / (BATCH * NPTS);
    const int rem = t % (BATCH * NPTS);
    const int b = rem / NPTS;
    const int i = rem % NPTS;

    float dist = g_dist[dir][b][i];
    int   idx  = g_idx [dir][b][i];
    float c    = (float)g_cnt[dir][b][idx];

    float w;
    if (dir == 0) {
        w = 1.0f / fmaxf(1.0f / c + 1e-6f, 1.0f);
    } else {
        w = 1.0f / (c + 1e-6f);
    }

    float e = expf(-dist * ALPHA);
    float contrib = (1.0f - e * w) * (1.0f / (2.0f * BATCH * NPTS));

    #pragma unroll
    for (int off = 16; off > 0; off >>= 1)
        contrib += __shfl_down_sync(0xFFFFFFFFu, contrib, off);

    __shared__ float warp_sums[8];
    const int lane = threadIdx.x & 31;
    const int wid  = threadIdx.x >> 5;
    if (lane == 0) warp_sums[wid] = contrib;
    __syncthreads();

    if (wid == 0) {
        float s = (lane < 8) ? warp_sums[lane] : 0.0f;
        #pragma unroll
        for (int off = 4; off > 0; off >>= 1)
            s += __shfl_down_sync(0xFFFFFFFFu, s, off);
        if (lane == 0) atomicAdd(out, s);
    }
}

// ---------------------------------------------------------------------------
// Launch
// ---------------------------------------------------------------------------
extern "C" void kernel_launch(void* const* d_in, const int* in_sizes, int n_in,
                              void* d_out, int out_size) {
    const float* xyz1 = (const float*)d_in[0];  // prediction [4,8192,3]
    const float* xyz2 = (const float*)d_in[1];  // ground truth [4,8192,3]
    float* out = (float*)d_out;

    (void)in_sizes; (void)n_in; (void)out_size;

    const int total = 2 * BATCH * NPTS;

    dacd_prep_kernel<<<(total + 255) / 256, 256>>>(xyz1, xyz2, out);

    {
        dim3 grid(NPTS / (THR_NN * IQ), BATCH, 2);   // (64, 4, 2) = 512 blocks
        dacd_nn_kernel<<<grid, THR_NN>>>();
    }

    dacd_loss_kernel<<<total / 256, 256>>>(out);
}